// round 8
// baseline (speedup 1.0000x reference)
#include <cuda_runtime.h>
#include <cuda_bf16.h>

// BERT embedding fused gather — ILP-batched version.
// out[t,:] = token_table[seq[t]] + mean_{g<cnt} genre_table[gids[seq[t],g]] + pos_table[t % L]
//
// Round-5 changes vs round-1 kernel (which was latency-bound: issue 51.7%,
// nothing saturated):
//  - 4 tokens per warp, single shot (no grid-stride loop): all long-latency
//    loads for 4 tokens issued back-to-back -> MLP ~12 per warp.
//  - seq read as one warp-uniform int4 (consecutive tokens per warp).
//  - genre_table read directly via __ldg (10.75 KB, L1-resident after warmup);
//    removes the per-block smem fill (13.7 MB L2 traffic) and __syncthreads.
//  - consecutive tokens -> consecutive pos rows (L % 4 == 0, no wrap in a
//    group) and 2 KB contiguous output per warp.

#define EMBED_VEC 32   // 128 floats = 32 float4
#define MAX_G 8
#define TPW 4          // tokens per warp

__global__ __launch_bounds__(256) void bert_embed_kernel(
    const int*    __restrict__ seq,          // [N]
    const float4* __restrict__ tok_table,    // [VOCAB][32]
    const float4* __restrict__ genre_table,  // [NG][32]
    const float4* __restrict__ pos_table,    // [MAX_LEN][32]
    const int4*   __restrict__ token_gids,   // [VOCAB][2]
    const int*    __restrict__ genre_counts, // [VOCAB]
    float4*       __restrict__ out,          // [N][32]
    int n_tokens, int L)
{
    const int lane = threadIdx.x & 31;
    const int w    = blockIdx.x * (blockDim.x >> 5) + (threadIdx.x >> 5);
    const int t0   = w * TPW;
    if (t0 >= n_tokens) return;

    // ---- gather all indices (warp-uniform loads) ----
    int tok[TPW];
    if (t0 + TPW <= n_tokens) {
        // t0 is 4-aligned and seq is 16B-aligned -> one uniform LDG.128
        const int4 s = __ldg((const int4*)(seq + t0));
        tok[0] = s.x; tok[1] = s.y; tok[2] = s.z; tok[3] = s.w;
    } else {
        #pragma unroll
        for (int i = 0; i < TPW; i++)
            tok[i] = (t0 + i < n_tokens) ? __ldg(&seq[t0 + i]) : 0;
    }

    // ---- issue ALL independent long-latency loads up front ----
    float4 tv[TPW];
    #pragma unroll
    for (int i = 0; i < TPW; i++)
        tv[i] = __ldg(&tok_table[tok[i] * EMBED_VEC + lane]);

    // pos rows: tokens consecutive; L % TPW == 0 and t0 % TPW == 0 means the
    // group never wraps, but keep a cheap per-element guard for generality.
    const int l0 = t0 % L;
    float4 pv[TPW];
    #pragma unroll
    for (int i = 0; i < TPW; i++) {
        int li = l0 + i;
        if (li >= L) li -= L;
        pv[i] = __ldg(&pos_table[li * EMBED_VEC + lane]);
    }

    int  cnt[TPW];
    int4 ga[TPW], gb[TPW];
    #pragma unroll
    for (int i = 0; i < TPW; i++) {
        cnt[i] = __ldg(&genre_counts[tok[i]]);
        ga[i]  = __ldg(&token_gids[tok[i] * 2 + 0]);
        gb[i]  = __ldg(&token_gids[tok[i] * 2 + 1]);
    }

    // ---- genre mean (L1-resident table) + combine + store ----
    #pragma unroll
    for (int i = 0; i < TPW; i++) {
        const int g[MAX_G] = { ga[i].x, ga[i].y, ga[i].z, ga[i].w,
                               gb[i].x, gb[i].y, gb[i].z, gb[i].w };
        float4 acc = make_float4(0.f, 0.f, 0.f, 0.f);
        #pragma unroll
        for (int j = 0; j < MAX_G; j++) {
            if (j < cnt[i]) {
                const float4 gv = __ldg(&genre_table[g[j] * EMBED_VEC + lane]);
                acc.x += gv.x; acc.y += gv.y; acc.z += gv.z; acc.w += gv.w;
            }
        }
        const float inv = 1.0f / (float)cnt[i];

        float4 o;
        o.x = tv[i].x + acc.x * inv + pv[i].x;
        o.y = tv[i].y + acc.y * inv + pv[i].y;
        o.z = tv[i].z + acc.z * inv + pv[i].z;
        o.w = tv[i].w + acc.w * inv + pv[i].w;

        if (t0 + i < n_tokens)
            out[(t0 + i) * EMBED_VEC + lane] = o;
    }
}

extern "C" void kernel_launch(void* const* d_in, const int* in_sizes, int n_in,
                              void* d_out, int out_size) {
    //   0: sequence        int32   [B*L] = 51200
    //   1: token_table     float32 [VOCAB*128]
    //   2: genre_table     float32 [(NG+1)*128]
    //   3: pos_table       float32 [MAX_LEN*128]
    //   4: token_genre_ids int32   [VOCAB*8]
    //   5: genre_counts    int32   [VOCAB]
    const int*    seq          = (const int*)   d_in[0];
    const float4* tok_table    = (const float4*)d_in[1];
    const float4* genre_table  = (const float4*)d_in[2];
    const float4* pos_table    = (const float4*)d_in[3];
    const int4*   token_gids   = (const int4*)  d_in[4];
    const int*    genre_counts = (const int*)   d_in[5];
    float4*       out          = (float4*)      d_out;

    const int n_tokens = in_sizes[0];         // 51200
    const int L        = in_sizes[3] / 128;   // 200

    const int threads    = 256;               // 8 warps/block
    const int n_groups   = (n_tokens + TPW - 1) / TPW;        // 12800 warps
    const int blocks     = (n_groups + 7) / 8;                // 1600 blocks

    bert_embed_kernel<<<blocks, threads>>>(seq, tok_table, genre_table,
                                           pos_table, token_gids, genre_counts,
                                           out, n_tokens, L);
}

// round 10
// speedup vs baseline: 1.5339x; 1.5339x over previous
#include <cuda_runtime.h>
#include <cuda_bf16.h>

// BERT embedding fused gather — round 8.
// out[t,:] = token_table[seq[t]] + mean_{g<cnt} genre_table[gids[seq[t],g]] + pos_table[t % L]
//
// R5 post-mortem: 4-token payload batching cost 82 regs -> occ 22.6% -> 23.2us.
// This version keeps per-warp vector state minimal (one token's worth) and gets
// memory-level parallelism from:
//   - warp -> (l, 4 consecutive batch rows): pos row loaded ONCE, reused 4x
//   - all 4 seq loads issued up front (independent L2 streams)
//   - 1-deep software pipeline: next token's gids/cnt/token-row prefetched
//     while current token's genre mean + combine executes
//   - genre table via __ldg (L1-resident 10.75 KB); predicated-off loads emit
//     no wavefronts, so genre traffic stays at avg 4.5 rows/token
// No smem, no __syncthreads.

#define EV    32   // 128 floats = 32 float4
#define MAX_G 8
#define BPW   4    // batch rows per warp (same l)

__global__ __launch_bounds__(256) void bert_embed_kernel(
    const int*    __restrict__ seq,          // [B*L]
    const float4* __restrict__ tok_table,    // [VOCAB][32]
    const float4* __restrict__ genre_table,  // [NG][32]
    const float4* __restrict__ pos_table,    // [MAX_LEN][32]
    const int4*   __restrict__ token_gids,   // [VOCAB][2]
    const int*    __restrict__ genre_counts, // [VOCAB]
    float4*       __restrict__ out,          // [B*L][32]
    int L, int B)
{
    const int lane = threadIdx.x & 31;
    const int w    = blockIdx.x * (blockDim.x >> 5) + (threadIdx.x >> 5);
    const int l    = w % L;
    const int b0   = (w / L) * BPW;
    if (b0 >= B) return;

    // pos row for this column: loaded once, reused for all BPW tokens.
    const float4 pv = __ldg(&pos_table[l * EV + lane]);

    // All seq reads issued up front (independent, warp-uniform).
    int tk[BPW];
    #pragma unroll
    for (int k = 0; k < BPW; k++) {
        const int b = b0 + k;
        tk[k] = (b < B) ? __ldg(&seq[b * L + l]) : 0;
    }

    // Prime the pipeline with token 0's metadata + embedding row.
    int4   ga  = __ldg(&token_gids[tk[0] * 2 + 0]);
    int4   gb  = __ldg(&token_gids[tk[0] * 2 + 1]);
    int    cnt = __ldg(&genre_counts[tk[0]]);
    float4 tv  = __ldg(&tok_table[tk[0] * EV + lane]);

    #pragma unroll
    for (int k = 0; k < BPW; k++) {
        // ---- prefetch next token's data (hides seq->tok dependent latency) ----
        int4 gaN = ga, gbN = gb; int cntN = 1; float4 tvN = tv;
        if (k + 1 < BPW) {
            const int tn = tk[k + 1];
            gaN  = __ldg(&token_gids[tn * 2 + 0]);
            gbN  = __ldg(&token_gids[tn * 2 + 1]);
            cntN = __ldg(&genre_counts[tn]);
            tvN  = __ldg(&tok_table[tn * EV + lane]);
        }

        // ---- genre mean for current token ----
        const int g[MAX_G] = { ga.x, ga.y, ga.z, ga.w,
                               gb.x, gb.y, gb.z, gb.w };
        float4 acc = make_float4(0.f, 0.f, 0.f, 0.f);
        #pragma unroll
        for (int j = 0; j < MAX_G; j++) {
            if (j < cnt) {   // predicated: off-iterations emit no L1 wavefront
                const float4 gv = __ldg(&genre_table[g[j] * EV + lane]);
                acc.x += gv.x; acc.y += gv.y; acc.z += gv.z; acc.w += gv.w;
            }
        }
        const float inv = 1.0f / (float)cnt;

        float4 o;
        o.x = tv.x + acc.x * inv + pv.x;
        o.y = tv.y + acc.y * inv + pv.y;
        o.z = tv.z + acc.z * inv + pv.z;
        o.w = tv.w + acc.w * inv + pv.w;

        const int b = b0 + k;
        if (b < B)
            out[(b * L + l) * EV + lane] = o;

        // rotate pipeline registers
        ga = gaN; gb = gbN; cnt = cntN; tv = tvN;
    }
}

extern "C" void kernel_launch(void* const* d_in, const int* in_sizes, int n_in,
                              void* d_out, int out_size) {
    //   0: sequence        int32   [B*L] = 51200
    //   1: token_table     float32 [VOCAB*128]
    //   2: genre_table     float32 [(NG+1)*128]
    //   3: pos_table       float32 [MAX_LEN*128]
    //   4: token_genre_ids int32   [VOCAB*8]
    //   5: genre_counts    int32   [VOCAB]
    const int*    seq          = (const int*)   d_in[0];
    const float4* tok_table    = (const float4*)d_in[1];
    const float4* genre_table  = (const float4*)d_in[2];
    const float4* pos_table    = (const float4*)d_in[3];
    const int4*   token_gids   = (const int4*)  d_in[4];
    const int*    genre_counts = (const int*)   d_in[5];
    float4*       out          = (float4*)      d_out;

    const int n_tokens = in_sizes[0];          // 51200
    const int L        = in_sizes[3] / 128;    // 200
    const int B        = n_tokens / L;         // 256

    const int warps_needed = L * ((B + BPW - 1) / BPW);  // 200*64 = 12800
    const int threads      = 256;                        // 8 warps/block
    const int blocks       = (warps_needed + 7) / 8;     // 1600

    bert_embed_kernel<<<blocks, threads>>>(seq, tok_table, genre_table,
                                           pos_table, token_gids, genre_counts,
                                           out, L, B);
}